// round 14
// baseline (speedup 1.0000x reference)
#include <cuda_runtime.h>
#include <cuda_bf16.h>
#include <cstdint>
#include <math.h>

// ---------------- problem constants ----------------
#define B_    4
#define L_    3136
#define DM_   192       // d_model
#define DIN_  384       // d_in
#define NS_   16        // n_state
#define KDIR_ 4
#define RED_  48
#define NCH_  49        // scan chunks
#define LCH_  64        // L_/NCH_
#define NR_   44        // dt_rank + 2*n_state
#define LOG2E 1.4426950408889634f

typedef unsigned long long u64;
typedef unsigned int u32;

// ---------------- f32x2 packed helpers (sm_103a FFMA2) ----------------
__device__ __forceinline__ u64 pack2(float lo, float hi) {
    u64 r; asm("mov.b64 %0,{%1,%2};" : "=l"(r) : "f"(lo), "f"(hi)); return r;
}
__device__ __forceinline__ void unpack2(u64 v, float& lo, float& hi) {
    asm("mov.b64 {%0,%1},%2;" : "=f"(lo), "=f"(hi) : "l"(v));
}
__device__ __forceinline__ u64 fma2(u64 a, u64 b, u64 c) {
    u64 d; asm("fma.rn.f32x2 %0,%1,%2,%3;" : "=l"(d) : "l"(a), "l"(b), "l"(c)); return d;
}
__device__ __forceinline__ u64 mul2(u64 a, u64 b) {
    u64 d; asm("mul.rn.f32x2 %0,%1,%2;" : "=l"(d) : "l"(a), "l"(b)); return d;
}
__device__ __forceinline__ float rcp_approx(float x) {
    float r; asm("rcp.approx.f32 %0,%1;" : "=f"(r) : "f"(x)); return r;
}

// ---------------- cp.async helpers ----------------
__device__ __forceinline__ u32 smem_u32(const void* p) {
    return (u32)__cvta_generic_to_shared(p);
}
__device__ __forceinline__ void cp_async16(u32 s, const void* g) {
    asm volatile("cp.async.cg.shared.global [%0], [%1], 16;" :: "r"(s), "l"(g));
}
__device__ __forceinline__ void cp_commit() {
    asm volatile("cp.async.commit_group;" ::: "memory");
}
template<int N> __device__ __forceinline__ void cp_wait() {
    asm volatile("cp.async.wait_group %0;" :: "n"(N) : "memory");
}

// ---------------- scratch (static device globals; no allocation) ----------------
__device__ float g_mask[B_ * L_];
__device__ unsigned char g_pok[DIN_];
__device__ __align__(16) float g_xz[(size_t)B_ * L_ * 2 * DIN_];            // (b,l,768)
__device__ __align__(16) float g_u[((size_t)KDIR_ * B_ * L_ + 128) * DIN_]; // (z,p,384) + pad
__device__ __align__(16) float g_xdbl[(size_t)KDIR_ * B_ * L_ * NR_];       // (z,p,44)
__device__ __align__(16) u64   g_Q[(size_t)KDIR_ * B_ * NCH_ * 8 * DIN_];   // pair-plane
__device__ float g_S[(size_t)KDIR_ * B_ * NCH_ * DIN_];
__device__ __align__(16) u64   g_Hs[(size_t)KDIR_ * B_ * NCH_ * 8 * DIN_];  // pair-plane
__device__ __align__(16) float g_y[(size_t)KDIR_ * B_ * L_ * DIN_];         // (z,l,384)
__device__ float g_gsum[KDIR_ * B_ * DIN_];
__device__ float g_catt[KDIR_ * B_ * DIN_];

// ---------------- direction permutation: scan position p -> original l ----------------
__device__ __forceinline__ int perm_idx(int k, int p) {
    int q = (k & 1) ? (L_ - 1 - p) : p;
    if (k < 2) return q;
    int wi = q % 7;
    int t  = q / 7;
    int hi = t % 7;
    int blk = t / 7;
    int wg = blk & 7, hg = blk >> 3;
    return (hg * 7 + hi) * 56 + wg * 7 + wi;
}

// rare exact-fallback path (A not the structured -(n+1) pattern)
__device__ __noinline__ void exp_general(float de, const float* __restrict__ A_log,
                                         int d, float* e) {
    #pragma unroll
    for (int n = 0; n < NS_; n++)
        e[n] = exp2f(de * (-__expf(A_log[d * NS_ + n])) * LOG2E);
}

// e2[i] = (r^(2i+1), r^(2i+2)) via shallow tree
__device__ __forceinline__ void decay_from_r(float r, u64* e2) {
    float r2 = r * r, r4 = r2 * r2, r8 = r4 * r4;
    u64 p2 = pack2(r2, r2), p4 = pack2(r4, r4), p8 = pack2(r8, r8);
    e2[0] = pack2(r, r2);
    e2[1] = mul2(e2[0], p2);
    e2[2] = mul2(e2[0], p4);
    e2[3] = mul2(e2[1], p4);
    e2[4] = mul2(e2[0], p8);
    e2[5] = mul2(e2[1], p8);
    e2[6] = mul2(e2[2], p8);
    e2[7] = mul2(e2[3], p8);
}

// ---------------- mask + gsum zero + pok precompute ----------------
__global__ void k_mask(const float* __restrict__ X, const float* __restrict__ MW,
                       const float* __restrict__ MB, const float* __restrict__ A_log) {
    int t = blockIdx.x * 256 + threadIdx.y * 32 + threadIdx.x;
    if (t < KDIR_ * B_ * DIN_) g_gsum[t] = 0.f;
    if (blockIdx.x == 0) {
        int tt = threadIdx.y * 32 + threadIdx.x;
        if (tt < DIN_) {
            bool p = true;
            #pragma unroll
            for (int n = 0; n < NS_; n++) {
                float an = -__expf(A_log[tt * NS_ + n]);
                if (fabsf(an + (float)(n + 1)) > 1e-4f * (float)(n + 1)) p = false;
            }
            g_pok[tt] = p ? 1 : 0;
        }
    }
    int row = blockIdx.x * 8 + threadIdx.y;
    if (row >= B_ * L_) return;
    int lane = threadIdx.x;
    const float* xr = X + (size_t)row * DM_;
    float s = 0.f;
    for (int i = lane; i < DM_; i += 32) s += xr[i] * MW[i];
    #pragma unroll
    for (int o = 16; o; o >>= 1) s += __shfl_xor_sync(0xFFFFFFFFu, s, o);
    if (lane == 0) g_mask[row] = (s + MB[0] > 0.f) ? 1.f : 0.f;
}

// ---------------- xz = x @ in_proj_w.T : M=12544, N=768, K=192 (FFMA2, cp.async) ----------------
__global__ __launch_bounds__(256) void k_xz(const float* __restrict__ X,
                                            const float* __restrict__ W) {
    __shared__ float4 As[2][64][9];
    __shared__ float4 Ws[2][64][9];
    int m0 = blockIdx.y * 64, n0 = blockIdx.x * 64;
    int tid = threadIdx.x;
    int tx = tid & 15, ty = tid >> 4;
    const float4* X4 = (const float4*)X;
    const float4* W4 = (const float4*)W;
    u64 acc2[4][4];
    #pragma unroll
    for (int i = 0; i < 4; i++)
        #pragma unroll
        for (int j = 0; j < 4; j++) acc2[i][j] = pack2(0.f, 0.f);
    {
        #pragma unroll
        for (int i = 0; i < 2; i++) {
            int idx = tid + i * 256;
            int rr = idx >> 3, kk = idx & 7;
            cp_async16(smem_u32(&As[0][rr][kk]), &X4[(size_t)(m0 + rr) * 48 + kk]);
            cp_async16(smem_u32(&Ws[0][rr][kk]), &W4[(size_t)(n0 + rr) * 48 + kk]);
        }
        cp_commit();
    }
    int buf = 0;
    #pragma unroll
    for (int it = 0; it < 6; it++) {
        if (it < 5) {
            int k0n = (it + 1) * 8;
            #pragma unroll
            for (int i = 0; i < 2; i++) {
                int idx = tid + i * 256;
                int rr = idx >> 3, kk = idx & 7;
                cp_async16(smem_u32(&As[buf ^ 1][rr][kk]), &X4[(size_t)(m0 + rr) * 48 + k0n + kk]);
                cp_async16(smem_u32(&Ws[buf ^ 1][rr][kk]), &W4[(size_t)(n0 + rr) * 48 + k0n + kk]);
            }
            cp_commit();
            cp_wait<1>();
        } else {
            cp_wait<0>();
        }
        __syncthreads();
        #pragma unroll
        for (int kq = 0; kq < 8; kq++) {
            ulonglong2 au[4];
            #pragma unroll
            for (int i = 0; i < 4; i++) au[i] = *(const ulonglong2*)&As[buf][ty * 4 + i][kq];
            #pragma unroll
            for (int j = 0; j < 4; j++) {
                ulonglong2 w = *(const ulonglong2*)&Ws[buf][tx + 16 * j][kq];
                #pragma unroll
                for (int i = 0; i < 4; i++) {
                    acc2[i][j] = fma2(au[i].x, w.x, acc2[i][j]);
                    acc2[i][j] = fma2(au[i].y, w.y, acc2[i][j]);
                }
            }
        }
        __syncthreads();
        buf ^= 1;
    }
    #pragma unroll
    for (int i = 0; i < 4; i++)
        #pragma unroll
        for (int j = 0; j < 4; j++) {
            float lo, hi; unpack2(acc2[i][j], lo, hi);
            g_xz[(size_t)(m0 + ty * 4 + i) * 768 + n0 + tx + 16 * j] = lo + hi;
        }
}

// ---------------- depthwise causal conv + silu + mask -> u (rolling window) ----------------
__global__ __launch_bounds__(128) void k_conv(const float* __restrict__ CW,
                                              const float* __restrict__ CB) {
    int z = blockIdx.z;
    int k = z >> 2, b = z & 3;
    int tx = threadIdx.x;
    int d = blockIdx.y * 128 + tx;
    int p0 = blockIdx.x * 64;
    __shared__ int ls[67];
    if (tx < 67) {
        int p = p0 - 3 + tx;
        ls[tx] = (p >= 0) ? perm_idx(k, p) : -1;
    }
    __syncthreads();
    float w0 = CW[d * 4 + 0], w1 = CW[d * 4 + 1], w2 = CW[d * 4 + 2], w3 = CW[d * 4 + 3];
    float cb = CB[d];
    size_t bL = (size_t)b * L_;
    float x0 = 0.f, x1 = 0.f, x2 = 0.f;
    {
        int l0 = ls[0], l1 = ls[1], l2 = ls[2];
        if (l0 >= 0) x0 = g_xz[(bL + l0) * 768 + d] * g_mask[bL + l0];
        if (l1 >= 0) x1 = g_xz[(bL + l1) * 768 + d] * g_mask[bL + l1];
        if (l2 >= 0) x2 = g_xz[(bL + l2) * 768 + d] * g_mask[bL + l2];
    }
    float* ob = g_u + ((size_t)z * L_ + p0) * DIN_ + d;
    #pragma unroll 4
    for (int j = 0; j < 64; j++) {
        int l = ls[j + 3];
        float m = g_mask[bL + l];
        float x3 = g_xz[(bL + l) * 768 + d] * m;
        float s = w0 * x0 + w1 * x1 + w2 * x2 + w3 * x3 + cb;
        float y = s / (1.f + __expf(-s));
        ob[(size_t)j * DIN_] = y * m;
        x0 = x1; x1 = x2; x2 = x3;
    }
}

// ---------------- x_dbl: scalar FFMA config (frozen) + cp.async double-buffer ----------------
__global__ __launch_bounds__(128) void k_xdbl(const float* __restrict__ XPW) {
    __shared__ float4 Us[2][128][9];
    __shared__ float4 Ws[2][NR_][9];
    int z = blockIdx.y;
    int k = z >> 2;
    int p0 = blockIdx.x * 128;
    int tid = threadIdx.x;
    int rq = tid & 3, pg = tid >> 2;   // pg 0..31
    const float4* U4 = (const float4*)g_u;
    const float4* W4 = (const float4*)XPW;
    float acc[4][11] = {};
    {
        #pragma unroll
        for (int i = 0; i < 8; i++) {
            int idx = tid + i * 128;
            int r = idx >> 3, kq = idx & 7;
            cp_async16(smem_u32(&Us[0][r][kq]), &U4[((size_t)z * L_ + p0 + r) * 96 + kq]);
        }
        #pragma unroll
        for (int i = 0; i < 3; i++) {
            int idx = tid + i * 128;
            if (idx < NR_ * 8) {
                int r = idx >> 3, kq = idx & 7;
                cp_async16(smem_u32(&Ws[0][r][kq]), &W4[((size_t)k * NR_ + r) * 96 + kq]);
            }
        }
        cp_commit();
    }
    int buf = 0;
    for (int it = 0; it < 12; it++) {
        if (it + 1 < 12) {
            int k0n = (it + 1) * 8;
            #pragma unroll
            for (int i = 0; i < 8; i++) {
                int idx = tid + i * 128;
                int r = idx >> 3, kq = idx & 7;
                cp_async16(smem_u32(&Us[buf ^ 1][r][kq]),
                           &U4[((size_t)z * L_ + p0 + r) * 96 + k0n + kq]);
            }
            #pragma unroll
            for (int i = 0; i < 3; i++) {
                int idx = tid + i * 128;
                if (idx < NR_ * 8) {
                    int r = idx >> 3, kq = idx & 7;
                    cp_async16(smem_u32(&Ws[buf ^ 1][r][kq]),
                               &W4[((size_t)k * NR_ + r) * 96 + k0n + kq]);
                }
            }
            cp_commit();
            cp_wait<1>();
        } else {
            cp_wait<0>();
        }
        __syncthreads();
        #pragma unroll
        for (int kq = 0; kq < 8; kq++) {
            float4 u4[4], w4[11];
            #pragma unroll
            for (int i = 0; i < 4; i++) u4[i] = Us[buf][pg * 4 + i][kq];
            #pragma unroll
            for (int j = 0; j < 11; j++) w4[j] = Ws[buf][rq + 4 * j][kq];
            #pragma unroll
            for (int i = 0; i < 4; i++)
                #pragma unroll
                for (int j = 0; j < 11; j++)
                    acc[i][j] += u4[i].x * w4[j].x + u4[i].y * w4[j].y +
                                 u4[i].z * w4[j].z + u4[i].w * w4[j].w;
        }
        __syncthreads();
        buf ^= 1;
    }
    #pragma unroll
    for (int i = 0; i < 4; i++) {
        int p = p0 + pg * 4 + i;
        if (p < L_) {
            float* ob = g_xdbl + ((size_t)z * L_ + p) * NR_;
            #pragma unroll
            for (int j = 0; j < 11; j++) ob[rq + 4 * j] = acc[i][j];
        }
    }
}

// ---------------- scan pass 1: local scan, x_dbl slab in smem, u prefetched ----------------
__global__ __launch_bounds__(128) void k_scan1(const float* __restrict__ A_log,
                                               const float* __restrict__ DTW,
                                               const float* __restrict__ DTB) {
    int z = blockIdx.z;
    int k = z >> 2;
    int tid = threadIdx.x;
    int d = blockIdx.y * 128 + tid;
    int c = blockIdx.x;
    __shared__ float4 sx[LCH_ * 11];
    {
        const float4* src = (const float4*)(g_xdbl + ((size_t)z * L_ + c * LCH_) * NR_);
        #pragma unroll
        for (int i = 0; i < 6; i++) {
            int idx = tid + i * 128;
            if (idx < LCH_ * 11) sx[idx] = src[idx];
        }
    }
    u64 wp[6];
    {
        const float* w = DTW + ((size_t)k * DIN_ + d) * 12;
        #pragma unroll
        for (int i = 0; i < 6; i++) wp[i] = pack2(w[2 * i], w[2 * i + 1]);
    }
    float bias = DTB[k * DIN_ + d];
    bool pok = (g_pok[d] != 0);
    const float* ul = g_u + ((size_t)z * L_ + c * LCH_) * DIN_ + d;
    u64 h2[8];
    #pragma unroll
    for (int i = 0; i < 8; i++) h2[i] = pack2(0.f, 0.f);
    float rprod = 1.f, sdel = 0.f;
    __syncthreads();
    float uu_c = ul[0];
    #pragma unroll 2
    for (int s = 0; s < LCH_; s++) {
        float uu_n = (s + 1 < LCH_) ? ul[(size_t)(s + 1) * DIN_] : 0.f;
        const ulonglong2* rp = (const ulonglong2*)&sx[s * 11];
        ulonglong2 X0 = rp[0], X1 = rp[1], X2 = rp[2];
        u64 s2 = mul2(X0.x, wp[0]);
        s2 = fma2(X0.y, wp[1], s2);
        s2 = fma2(X1.x, wp[2], s2);
        s2 = fma2(X1.y, wp[3], s2);
        s2 = fma2(X2.x, wp[4], s2);
        s2 = fma2(X2.y, wp[5], s2);
        float lo, hi; unpack2(s2, lo, hi);
        float sv = lo + hi + bias;
        float t = __expf(sv);
        float w1t = 1.f + t;
        float de = (sv > 20.f) ? sv : __logf(w1t);
        float du = de * uu_c;
        u64 du2 = pack2(du, du);
        u64 e2[8];
        if (pok) {
            float r = rcp_approx(w1t);      // exp(-softplus(sv))
            decay_from_r(r, e2);
            rprod *= r;
        } else {
            float ee[16];
            exp_general(de, A_log, d, ee);
            #pragma unroll
            for (int i = 0; i < 8; i++) e2[i] = pack2(ee[2 * i], ee[2 * i + 1]);
            sdel += de;
        }
        ulonglong2 B0 = rp[3], B1 = rp[4], B2 = rp[5], B3 = rp[6];
        h2[0] = fma2(e2[0], h2[0], mul2(du2, B0.x));
        h2[1] = fma2(e2[1], h2[1], mul2(du2, B0.y));
        h2[2] = fma2(e2[2], h2[2], mul2(du2, B1.x));
        h2[3] = fma2(e2[3], h2[3], mul2(du2, B1.y));
        h2[4] = fma2(e2[4], h2[4], mul2(du2, B2.x));
        h2[5] = fma2(e2[5], h2[5], mul2(du2, B2.y));
        h2[6] = fma2(e2[6], h2[6], mul2(du2, B3.x));
        h2[7] = fma2(e2[7], h2[7], mul2(du2, B3.y));
        uu_c = uu_n;
    }
    u64* q = g_Q + ((size_t)z * NCH_ + c) * 8 * DIN_ + d;
    #pragma unroll
    for (int i = 0; i < 8; i++) q[(size_t)i * DIN_] = h2[i];
    g_S[((size_t)z * NCH_ + c) * DIN_ + d] = pok ? rprod : sdel;
}

// ---------------- scan fix: prefix over chunks (parallel over z x dgroup, prefetched) ----------------
__global__ __launch_bounds__(128) void k_fix(const float* __restrict__ A_log) {
    int z = blockIdx.x;
    int dg = blockIdx.y;
    int d = dg * 128 + threadIdx.x;
    bool pok = (g_pok[d] != 0);
    float a2[NS_];
    if (!pok) {
        #pragma unroll
        for (int n = 0; n < NS_; n++)
            a2[n] = -__expf(A_log[d * NS_ + n]) * LOG2E;
    }
    const u64* Q = g_Q + (size_t)z * NCH_ * 8 * DIN_ + d;
    u64* H = g_Hs + (size_t)z * NCH_ * 8 * DIN_ + d;
    const float* S = g_S + (size_t)z * NCH_ * DIN_ + d;
    u64 hs2[8];
    #pragma unroll
    for (int i = 0; i < 8; i++) hs2[i] = pack2(0.f, 0.f);
    u64 qc[8]; float Sc;
    #pragma unroll
    for (int i = 0; i < 8; i++) qc[i] = Q[(size_t)i * DIN_];
    Sc = S[0];
    for (int c = 0; c < NCH_; c++) {
        u64 qn[8]; float Sn = 0.f;
        if (c + 1 < NCH_) {
            const u64* Qn = Q + (size_t)(c + 1) * 8 * DIN_;
            #pragma unroll
            for (int i = 0; i < 8; i++) qn[i] = Qn[(size_t)i * DIN_];
            Sn = S[(size_t)(c + 1) * DIN_];
        }
        u64* Hc = H + (size_t)c * 8 * DIN_;
        #pragma unroll
        for (int i = 0; i < 8; i++) Hc[(size_t)i * DIN_] = hs2[i];
        u64 e2[8];
        if (pok) {
            decay_from_r(Sc, e2);        // Sc = prod of r over chunk
        } else {
            float ee[16];
            #pragma unroll
            for (int n = 0; n < NS_; n++) ee[n] = exp2f(a2[n] * Sc);
            #pragma unroll
            for (int i = 0; i < 8; i++) e2[i] = pack2(ee[2 * i], ee[2 * i + 1]);
        }
        #pragma unroll
        for (int i = 0; i < 8; i++) hs2[i] = fma2(e2[i], hs2[i], qc[i]);
        #pragma unroll
        for (int i = 0; i < 8; i++) qc[i] = qn[i];
        Sc = Sn;
    }
}

// ---------------- scan pass 2: replay with h_start, smem slab, u/z prefetched ----------------
__global__ __launch_bounds__(128) void k_scan2(const float* __restrict__ A_log,
                                               const float* __restrict__ DTW,
                                               const float* __restrict__ DTB,
                                               const float* __restrict__ Dsk) {
    int z = blockIdx.z;
    int k = z >> 2, b = z & 3;
    int tid = threadIdx.x;
    int d = blockIdx.y * 128 + tid;
    int c = blockIdx.x;
    __shared__ float4 sx[LCH_ * 11];
    __shared__ int ls[LCH_];
    {
        const float4* src = (const float4*)(g_xdbl + ((size_t)z * L_ + c * LCH_) * NR_);
        #pragma unroll
        for (int i = 0; i < 6; i++) {
            int idx = tid + i * 128;
            if (idx < LCH_ * 11) sx[idx] = src[idx];
        }
    }
    if (tid < LCH_) ls[tid] = perm_idx(k, c * LCH_ + tid);
    u64 wp[6];
    {
        const float* w = DTW + ((size_t)k * DIN_ + d) * 12;
        #pragma unroll
        for (int i = 0; i < 6; i++) wp[i] = pack2(w[2 * i], w[2 * i + 1]);
    }
    float bias = DTB[k * DIN_ + d];
    bool pok = (g_pok[d] != 0);
    const float* ul = g_u + ((size_t)z * L_ + c * LCH_) * DIN_ + d;
    const u64* H = g_Hs + ((size_t)z * NCH_ + c) * 8 * DIN_ + d;
    u64 h2[8];
    #pragma unroll
    for (int i = 0; i < 8; i++) h2[i] = H[(size_t)i * DIN_];
    float dsk = Dsk[d];
    size_t bL = (size_t)b * L_;
    __syncthreads();
    float uu_c = ul[0];
    int l_c = ls[0];
    float zv_c = g_xz[(bL + l_c) * (2 * DIN_) + DIN_ + d];
    #pragma unroll 2
    for (int s = 0; s < LCH_; s++) {
        float uu_n = 0.f, zv_n = 0.f; int l_n = 0;
        if (s + 1 < LCH_) {
            uu_n = ul[(size_t)(s + 1) * DIN_];
            l_n = ls[s + 1];
            zv_n = g_xz[(bL + l_n) * (2 * DIN_) + DIN_ + d];
        }
        const ulonglong2* rp = (const ulonglong2*)&sx[s * 11];
        ulonglong2 X0 = rp[0], X1 = rp[1], X2 = rp[2];
        u64 s2 = mul2(X0.x, wp[0]);
        s2 = fma2(X0.y, wp[1], s2);
        s2 = fma2(X1.x, wp[2], s2);
        s2 = fma2(X1.y, wp[3], s2);
        s2 = fma2(X2.x, wp[4], s2);
        s2 = fma2(X2.y, wp[5], s2);
        float lo, hi; unpack2(s2, lo, hi);
        float sv = lo + hi + bias;
        float t = __expf(sv);
        float w1t = 1.f + t;
        float de = (sv > 20.f) ? sv : __logf(w1t);
        float du = de * uu_c;
        u64 du2 = pack2(du, du);
        u64 e2[8];
        if (pok) {
            float r = rcp_approx(w1t);
            decay_from_r(r, e2);
        } else {
            float ee[16];
            exp_general(de, A_log, d, ee);
            #pragma unroll
            for (int i = 0; i < 8; i++) e2[i] = pack2(ee[2 * i], ee[2 * i + 1]);
        }
        ulonglong2 B0 = rp[3], B1 = rp[4], B2 = rp[5], B3 = rp[6];
        ulonglong2 C0 = rp[7], C1 = rp[8], C2 = rp[9], C3 = rp[10];
        h2[0] = fma2(e2[0], h2[0], mul2(du2, B0.x));
        h2[1] = fma2(e2[1], h2[1], mul2(du2, B0.y));
        h2[2] = fma2(e2[2], h2[2], mul2(du2, B1.x));
        h2[3] = fma2(e2[3], h2[3], mul2(du2, B1.y));
        h2[4] = fma2(e2[4], h2[4], mul2(du2, B2.x));
        h2[5] = fma2(e2[5], h2[5], mul2(du2, B2.y));
        h2[6] = fma2(e2[6], h2[6], mul2(du2, B3.x));
        h2[7] = fma2(e2[7], h2[7], mul2(du2, B3.y));
        u64 y2 = mul2(h2[0], C0.x);
        y2 = fma2(h2[1], C0.y, y2);
        y2 = fma2(h2[2], C1.x, y2);
        y2 = fma2(h2[3], C1.y, y2);
        y2 = fma2(h2[4], C2.x, y2);
        y2 = fma2(h2[5], C2.y, y2);
        y2 = fma2(h2[6], C3.x, y2);
        y2 = fma2(h2[7], C3.y, y2);
        float ylo, yhi; unpack2(y2, ylo, yhi);
        float y = ylo + yhi + dsk * uu_c;
        y *= zv_c / (1.f + __expf(-zv_c));
        g_y[((size_t)z * L_ + l_c) * DIN_ + d] = y;
        uu_c = uu_n; zv_c = zv_n; l_c = l_n;
    }
}

// ---------------- LayerNorm over d, warp-per-row x2 ILP, accumulate per-(z,d) sum of xn ----------------
__global__ __launch_bounds__(384) void k_lnstats(const float* __restrict__ G,
                                                 const float* __restrict__ Bt) {
    int kdir = blockIdx.z, b = blockIdx.y;
    int z = kdir * B_ + b;
    int tid = threadIdx.x;
    int w = tid >> 5, lane = tid & 31;
    int gw = blockIdx.x * 12 + w;
    float gr[12], br[12], acc[12];
    #pragma unroll
    for (int j = 0; j < 12; j++) {
        int d = lane + 32 * j;
        gr[j] = G[d]; br[j] = Bt[d]; acc[j] = 0.f;
    }
    int l = gw;
    for (; l + 192 < L_; l += 384) {
        const float* yr0 = g_y + ((size_t)z * L_ + l) * DIN_;
        const float* yr1 = g_y + ((size_t)z * L_ + l + 192) * DIN_;
        float v0[12], v1[12];
        float sa0 = 0.f, sb0 = 0.f, sa1 = 0.f, sb1 = 0.f;
        #pragma unroll
        for (int j = 0; j < 12; j++) {
            v0[j] = yr0[lane + 32 * j];
            v1[j] = yr1[lane + 32 * j];
        }
        #pragma unroll
        for (int j = 0; j < 12; j++) {
            sa0 += v0[j]; sb0 += v0[j] * v0[j];
            sa1 += v1[j]; sb1 += v1[j] * v1[j];
        }
        #pragma unroll
        for (int o = 16; o; o >>= 1) {
            sa0 += __shfl_xor_sync(0xFFFFFFFFu, sa0, o);
            sb0 += __shfl_xor_sync(0xFFFFFFFFu, sb0, o);
            sa1 += __shfl_xor_sync(0xFFFFFFFFu, sa1, o);
            sb1 += __shfl_xor_sync(0xFFFFFFFFu, sb1, o);
        }
        float mu0 = sa0 * (1.f / DIN_);
        float rstd0 = rsqrtf(sb0 * (1.f / DIN_) - mu0 * mu0 + 1e-5f);
        float mu1 = sa1 * (1.f / DIN_);
        float rstd1 = rsqrtf(sb1 * (1.f / DIN_) - mu1 * mu1 + 1e-5f);
        #pragma unroll
        for (int j = 0; j < 12; j++) {
            acc[j] += (v0[j] - mu0) * rstd0 * gr[j] + br[j];
            acc[j] += (v1[j] - mu1) * rstd1 * gr[j] + br[j];
        }
    }
    for (; l < L_; l += 192) {
        const float* yr = g_y + ((size_t)z * L_ + l) * DIN_;
        float v[12];
        float s1 = 0.f, s2 = 0.f;
        #pragma unroll
        for (int j = 0; j < 12; j++) {
            v[j] = yr[lane + 32 * j];
            s1 += v[j];
            s2 += v[j] * v[j];
        }
        #pragma unroll
        for (int o = 16; o; o >>= 1) {
            s1 += __shfl_xor_sync(0xFFFFFFFFu, s1, o);
            s2 += __shfl_xor_sync(0xFFFFFFFFu, s2, o);
        }
        float mu = s1 * (1.f / DIN_);
        float var = s2 * (1.f / DIN_) - mu * mu;
        float rstd = rsqrtf(var + 1e-5f);
        #pragma unroll
        for (int j = 0; j < 12; j++)
            acc[j] += (v[j] - mu) * rstd * gr[j] + br[j];
    }
    #pragma unroll
    for (int j = 0; j < 12; j++)
        atomicAdd(&g_gsum[z * DIN_ + lane + 32 * j], acc[j]);
}

// ---------------- channel attention ----------------
__global__ void k_attn(const float* __restrict__ RW, const float* __restrict__ RB,
                       const float* __restrict__ SW, const float* __restrict__ SB) {
    int z = blockIdx.x;
    __shared__ float gg[DIN_];
    __shared__ float tt[RED_];
    int d = threadIdx.x;
    int lane = d & 31, wid = d >> 5;
    gg[d] = g_gsum[z * DIN_ + d] * (1.f / (float)L_);
    __syncthreads();
    #pragma unroll
    for (int jj = 0; jj < 4; jj++) {
        int j = wid * 4 + jj;
        float s = 0.f;
        for (int i = lane; i < DIN_; i += 32) s += gg[i] * RW[(size_t)j * DIN_ + i];
        #pragma unroll
        for (int o = 16; o; o >>= 1) s += __shfl_xor_sync(0xFFFFFFFFu, s, o);
        if (lane == 0) {
            float v = s + RB[j];
            tt[j] = 0.5f * v * (1.f + erff(v * 0.70710678118f));
        }
    }
    __syncthreads();
    float s = SB[d];
    #pragma unroll
    for (int j = 0; j < RED_; j++) s += tt[j] * SW[(size_t)d * RED_ + j];
    g_catt[z * DIN_ + d] = 1.f / (1.f + __expf(-s));
}

// ---------------- out = (sum_k y_k * catt_k) @ out_proj.T + bias (FFMA2, y prefetch) ----------------
__global__ __launch_bounds__(128) void k_out(const float* __restrict__ W,
                                             const float* __restrict__ BI,
                                             float* __restrict__ OUT) {
    __shared__ float4 As[16][9];
    __shared__ float4 Ws[192][9];
    int m0 = blockIdx.x * 16;
    int b = m0 / L_;
    int l0 = m0 - b * L_;
    int tid = threadIdx.x;
    int tx = tid & 31, ty = tid >> 5;   // ty 0..3
    int ar = tid >> 3, akq = tid & 7;   // As loader role
    const float4* Y4 = (const float4*)g_y;
    const float4* C4 = (const float4*)g_catt;
    const float4* W4 = (const float4*)W;
    u64 acc2[4][6];
    #pragma unroll
    for (int i = 0; i < 4; i++)
        #pragma unroll
        for (int j = 0; j < 6; j++) acc2[i][j] = pack2(0.f, 0.f);
    // preload y stream for k0 = 0
    float4 ycur[KDIR_];
    #pragma unroll
    for (int dir = 0; dir < KDIR_; dir++)
        ycur[dir] = Y4[((size_t)(dir * B_ + b) * L_ + l0 + ar) * 96 + akq];
    for (int it = 0; it < 12; it++) {
        int k0 = it * 8;
        __syncthreads();
        {
            float4 s = {0.f, 0.f, 0.f, 0.f};
            #pragma unroll
            for (int dir = 0; dir < KDIR_; dir++) {
                float4 c4 = C4[(size_t)(dir * B_ + b) * 96 + k0 + akq];
                s.x += ycur[dir].x * c4.x; s.y += ycur[dir].y * c4.y;
                s.z += ycur[dir].z * c4.z; s.w += ycur[dir].w * c4.w;
            }
            As[ar][akq] = s;
        }
        #pragma unroll
        for (int i = 0; i < 12; i++) {
            int idx = tid + i * 128;
            int r = idx >> 3, kq = idx & 7;
            Ws[r][kq] = W4[(size_t)r * 96 + k0 + kq];
        }
        __syncthreads();
        if (it + 1 < 12) {
            int k0n = k0 + 8;
            #pragma unroll
            for (int dir = 0; dir < KDIR_; dir++)
                ycur[dir] = Y4[((size_t)(dir * B_ + b) * L_ + l0 + ar) * 96 + k0n + akq];
        }
        #pragma unroll
        for (int kq = 0; kq < 8; kq++) {
            ulonglong2 au[4];
            #pragma unroll
            for (int i = 0; i < 4; i++) au[i] = *(const ulonglong2*)&As[ty * 4 + i][kq];
            #pragma unroll
            for (int j = 0; j < 6; j++) {
                ulonglong2 w = *(const ulonglong2*)&Ws[tx + 32 * j][kq];
                #pragma unroll
                for (int i = 0; i < 4; i++) {
                    acc2[i][j] = fma2(au[i].x, w.x, acc2[i][j]);
                    acc2[i][j] = fma2(au[i].y, w.y, acc2[i][j]);
                }
            }
        }
    }
    #pragma unroll
    for (int i = 0; i < 4; i++)
        #pragma unroll
        for (int j = 0; j < 6; j++) {
            float lo, hi; unpack2(acc2[i][j], lo, hi);
            OUT[(size_t)(m0 + ty * 4 + i) * DM_ + tx + 32 * j] = lo + hi + BI[tx + 32 * j];
        }
}

// ---------------- launch ----------------
extern "C" void kernel_launch(void* const* d_in, const int* in_sizes, int n_in,
                              void* d_out, int out_size) {
    const float* x          = (const float*)d_in[0];
    const float* in_proj_w  = (const float*)d_in[1];
    const float* conv_w     = (const float*)d_in[2];
    const float* conv_b     = (const float*)d_in[3];
    const float* x_proj_w   = (const float*)d_in[4];
    const float* dt_w       = (const float*)d_in[5];
    const float* dt_b       = (const float*)d_in[6];
    const float* A_log      = (const float*)d_in[7];
    const float* D_skip     = (const float*)d_in[8];
    const float* out_proj_w = (const float*)d_in[9];
    const float* out_proj_b = (const float*)d_in[10];
    const float* ln_g       = (const float*)d_in[11];
    const float* ln_b       = (const float*)d_in[12];
    const float* red_w      = (const float*)d_in[13];
    const float* red_b      = (const float*)d_in[14];
    const float* sel_w      = (const float*)d_in[15];
    const float* sel_b      = (const float*)d_in[16];
    const float* mask_w     = (const float*)d_in[17];
    const float* mask_b     = (const float*)d_in[18];
    float* out = (float*)d_out;

    k_mask<<<dim3((B_ * L_ + 7) / 8), dim3(32, 8)>>>(x, mask_w, mask_b, A_log);
    k_xz<<<dim3(12, 196), 256>>>(x, in_proj_w);
    k_conv<<<dim3(49, 3, KDIR_ * B_), 128>>>(conv_w, conv_b);
    k_xdbl<<<dim3(25, KDIR_ * B_), 128>>>(x_proj_w);
    k_scan1<<<dim3(NCH_, 3, KDIR_ * B_), 128>>>(A_log, dt_w, dt_b);
    k_fix<<<dim3(KDIR_ * B_, 3), 128>>>(A_log);
    k_scan2<<<dim3(NCH_, 3, KDIR_ * B_), 128>>>(A_log, dt_w, dt_b, D_skip);
    k_lnstats<<<dim3(16, B_, KDIR_), 384>>>(ln_g, ln_b);
    k_attn<<<KDIR_ * B_, DIN_>>>(red_w, red_b, sel_w, sel_b);
    k_out<<<dim3(784), 128>>>(out_proj_w, out_proj_b, out);
}

// round 15
// speedup vs baseline: 2.0677x; 2.0677x over previous
#include <cuda_runtime.h>
#include <cuda_bf16.h>
#include <cstdint>
#include <math.h>

// ---------------- problem constants ----------------
#define B_    4
#define L_    3136
#define DM_   192       // d_model
#define DIN_  384       // d_in
#define NS_   16        // n_state
#define KDIR_ 4
#define RED_  48
#define NCH_  49        // scan chunks
#define LCH_  64        // L_/NCH_
#define NR_   44        // dt_rank + 2*n_state
#define LOG2E 1.4426950408889634f

typedef unsigned long long u64;
typedef unsigned int u32;

// ---------------- f32x2 packed helpers (sm_103a FFMA2) ----------------
__device__ __forceinline__ u64 pack2(float lo, float hi) {
    u64 r; asm("mov.b64 %0,{%1,%2};" : "=l"(r) : "f"(lo), "f"(hi)); return r;
}
__device__ __forceinline__ void unpack2(u64 v, float& lo, float& hi) {
    asm("mov.b64 {%0,%1},%2;" : "=f"(lo), "=f"(hi) : "l"(v));
}
__device__ __forceinline__ u64 fma2(u64 a, u64 b, u64 c) {
    u64 d; asm("fma.rn.f32x2 %0,%1,%2,%3;" : "=l"(d) : "l"(a), "l"(b), "l"(c)); return d;
}
__device__ __forceinline__ u64 mul2(u64 a, u64 b) {
    u64 d; asm("mul.rn.f32x2 %0,%1,%2;" : "=l"(d) : "l"(a), "l"(b)); return d;
}
__device__ __forceinline__ float rcp_approx(float x) {
    float r; asm("rcp.approx.f32 %0,%1;" : "=f"(r) : "f"(x)); return r;
}

// ---------------- cp.async helpers ----------------
__device__ __forceinline__ u32 smem_u32(const void* p) {
    return (u32)__cvta_generic_to_shared(p);
}
__device__ __forceinline__ void cp_async16(u32 s, const void* g) {
    asm volatile("cp.async.cg.shared.global [%0], [%1], 16;" :: "r"(s), "l"(g));
}
__device__ __forceinline__ void cp_commit() {
    asm volatile("cp.async.commit_group;" ::: "memory");
}
template<int N> __device__ __forceinline__ void cp_wait() {
    asm volatile("cp.async.wait_group %0;" :: "n"(N) : "memory");
}

// ---------------- scratch (static device globals; no allocation) ----------------
__device__ float g_mask[B_ * L_];
__device__ __align__(16) float g_xz[(size_t)B_ * L_ * 2 * DIN_];            // (b,l,768)
__device__ __align__(16) float g_u[((size_t)KDIR_ * B_ * L_ + 128) * DIN_]; // (z,p,384) + pad
__device__ __align__(16) float g_xdbl[(size_t)KDIR_ * B_ * L_ * NR_];       // (z,p,44)
__device__ __align__(16) u64   g_Q[(size_t)KDIR_ * B_ * NCH_ * 8 * DIN_];   // pair-plane
__device__ float g_S[(size_t)KDIR_ * B_ * NCH_ * DIN_];
__device__ __align__(16) u64   g_Hs[(size_t)KDIR_ * B_ * NCH_ * 8 * DIN_];  // pair-plane
__device__ __align__(16) float g_y[(size_t)KDIR_ * B_ * L_ * DIN_];         // (z,l,384)
__device__ float g_gsum[KDIR_ * B_ * DIN_];
__device__ float g_catt[KDIR_ * B_ * DIN_];

// ---------------- direction permutation: scan position p -> original l ----------------
__device__ __forceinline__ int perm_idx(int k, int p) {
    int q = (k & 1) ? (L_ - 1 - p) : p;
    if (k < 2) return q;
    int wi = q % 7;
    int t  = q / 7;
    int hi = t % 7;
    int blk = t / 7;
    int wg = blk & 7, hg = blk >> 3;
    return (hg * 7 + hi) * 56 + wg * 7 + wi;
}

// rare exact-fallback path (A not the structured -(n+1) pattern)
__device__ __noinline__ void exp_general(float de, const float* __restrict__ A_log,
                                         int d, float* e) {
    #pragma unroll
    for (int n = 0; n < NS_; n++)
        e[n] = exp2f(de * (-__expf(A_log[d * NS_ + n])) * LOG2E);
}

// e2[i] = (r^(2i+1), r^(2i+2)) via shallow tree
__device__ __forceinline__ void decay_from_r(float r, u64* e2) {
    float r2 = r * r, r4 = r2 * r2, r8 = r4 * r4;
    u64 p2 = pack2(r2, r2), p4 = pack2(r4, r4), p8 = pack2(r8, r8);
    e2[0] = pack2(r, r2);
    e2[1] = mul2(e2[0], p2);
    e2[2] = mul2(e2[0], p4);
    e2[3] = mul2(e2[1], p4);
    e2[4] = mul2(e2[0], p8);
    e2[5] = mul2(e2[1], p8);
    e2[6] = mul2(e2[2], p8);
    e2[7] = mul2(e2[3], p8);
}

// ---------------- mask + gsum zero ----------------
__global__ void k_mask(const float* __restrict__ X, const float* __restrict__ MW,
                       const float* __restrict__ MB) {
    int t = blockIdx.x * 256 + threadIdx.y * 32 + threadIdx.x;
    if (t < KDIR_ * B_ * DIN_) g_gsum[t] = 0.f;
    int row = blockIdx.x * 8 + threadIdx.y;
    if (row >= B_ * L_) return;
    int lane = threadIdx.x;
    const float* xr = X + (size_t)row * DM_;
    float s = 0.f;
    for (int i = lane; i < DM_; i += 32) s += xr[i] * MW[i];
    #pragma unroll
    for (int o = 16; o; o >>= 1) s += __shfl_xor_sync(0xFFFFFFFFu, s, o);
    if (lane == 0) g_mask[row] = (s + MB[0] > 0.f) ? 1.f : 0.f;
}

// ---------------- xz = x @ in_proj_w.T : M=12544, N=768, K=192 (FFMA2, ping-pong) ----------------
__global__ __launch_bounds__(256) void k_xz(const float* __restrict__ X,
                                            const float* __restrict__ W) {
    __shared__ float4 As[2][64][9];
    __shared__ float4 Ws[2][64][9];
    int m0 = blockIdx.y * 64, n0 = blockIdx.x * 64;
    int tid = threadIdx.x;
    int tx = tid & 15, ty = tid >> 4;
    const float4* X4 = (const float4*)X;
    const float4* W4 = (const float4*)W;
    u64 acc2[4][4];
    #pragma unroll
    for (int i = 0; i < 4; i++)
        #pragma unroll
        for (int j = 0; j < 4; j++) acc2[i][j] = pack2(0.f, 0.f);
    #pragma unroll
    for (int i = 0; i < 2; i++) {
        int idx = tid + i * 256;
        int rr = idx >> 3, kk = idx & 7;
        As[0][rr][kk] = X4[(size_t)(m0 + rr) * 48 + kk];
        Ws[0][rr][kk] = W4[(size_t)(n0 + rr) * 48 + kk];
    }
    __syncthreads();
    int buf = 0;
    #pragma unroll
    for (int it = 0; it < 6; it++) {
        float4 ra[2], rw[2];
        if (it < 5) {
            int k0n = (it + 1) * 8;
            #pragma unroll
            for (int i = 0; i < 2; i++) {
                int idx = tid + i * 256;
                int rr = idx >> 3, kk = idx & 7;
                ra[i] = X4[(size_t)(m0 + rr) * 48 + k0n + kk];
                rw[i] = W4[(size_t)(n0 + rr) * 48 + k0n + kk];
            }
        }
        #pragma unroll
        for (int kq = 0; kq < 8; kq++) {
            ulonglong2 au[4];
            #pragma unroll
            for (int i = 0; i < 4; i++) au[i] = *(const ulonglong2*)&As[buf][ty * 4 + i][kq];
            #pragma unroll
            for (int j = 0; j < 4; j++) {
                ulonglong2 w = *(const ulonglong2*)&Ws[buf][tx + 16 * j][kq];
                #pragma unroll
                for (int i = 0; i < 4; i++) {
                    acc2[i][j] = fma2(au[i].x, w.x, acc2[i][j]);
                    acc2[i][j] = fma2(au[i].y, w.y, acc2[i][j]);
                }
            }
        }
        if (it < 5) {
            #pragma unroll
            for (int i = 0; i < 2; i++) {
                int idx = tid + i * 256;
                int rr = idx >> 3, kk = idx & 7;
                As[buf ^ 1][rr][kk] = ra[i];
                Ws[buf ^ 1][rr][kk] = rw[i];
            }
        }
        __syncthreads();
        buf ^= 1;
    }
    #pragma unroll
    for (int i = 0; i < 4; i++)
        #pragma unroll
        for (int j = 0; j < 4; j++) {
            float lo, hi; unpack2(acc2[i][j], lo, hi);
            g_xz[(size_t)(m0 + ty * 4 + i) * 768 + n0 + tx + 16 * j] = lo + hi;
        }
}

// ---------------- depthwise causal conv + silu + mask -> u (rolling window) ----------------
__global__ __launch_bounds__(128) void k_conv(const float* __restrict__ CW,
                                              const float* __restrict__ CB) {
    int z = blockIdx.z;
    int k = z >> 2, b = z & 3;
    int tx = threadIdx.x;
    int d = blockIdx.y * 128 + tx;
    int p0 = blockIdx.x * 64;
    __shared__ int ls[67];
    if (tx < 67) {
        int p = p0 - 3 + tx;
        ls[tx] = (p >= 0) ? perm_idx(k, p) : -1;
    }
    __syncthreads();
    float w0 = CW[d * 4 + 0], w1 = CW[d * 4 + 1], w2 = CW[d * 4 + 2], w3 = CW[d * 4 + 3];
    float cb = CB[d];
    size_t bL = (size_t)b * L_;
    float x0 = 0.f, x1 = 0.f, x2 = 0.f;
    {
        int l0 = ls[0], l1 = ls[1], l2 = ls[2];
        if (l0 >= 0) x0 = g_xz[(bL + l0) * 768 + d] * g_mask[bL + l0];
        if (l1 >= 0) x1 = g_xz[(bL + l1) * 768 + d] * g_mask[bL + l1];
        if (l2 >= 0) x2 = g_xz[(bL + l2) * 768 + d] * g_mask[bL + l2];
    }
    float* ob = g_u + ((size_t)z * L_ + p0) * DIN_ + d;
    #pragma unroll 4
    for (int j = 0; j < 64; j++) {
        int l = ls[j + 3];
        float m = g_mask[bL + l];
        float x3 = g_xz[(bL + l) * 768 + d] * m;
        float s = w0 * x0 + w1 * x1 + w2 * x2 + w3 * x3 + cb;
        float y = s / (1.f + __expf(-s));
        ob[(size_t)j * DIN_] = y * m;
        x0 = x1; x1 = x2; x2 = x3;
    }
}

// ---------------- x_dbl: scalar FFMA config (frozen) + cp.async double-buffer ----------------
__global__ __launch_bounds__(128) void k_xdbl(const float* __restrict__ XPW) {
    __shared__ float4 Us[2][128][9];
    __shared__ float4 Ws[2][NR_][9];
    int z = blockIdx.y;
    int k = z >> 2;
    int p0 = blockIdx.x * 128;
    int tid = threadIdx.x;
    int rq = tid & 3, pg = tid >> 2;   // pg 0..31
    const float4* U4 = (const float4*)g_u;
    const float4* W4 = (const float4*)XPW;
    float acc[4][11] = {};
    // preload chunk 0
    {
        #pragma unroll
        for (int i = 0; i < 8; i++) {
            int idx = tid + i * 128;
            int r = idx >> 3, kq = idx & 7;
            cp_async16(smem_u32(&Us[0][r][kq]), &U4[((size_t)z * L_ + p0 + r) * 96 + kq]);
        }
        #pragma unroll
        for (int i = 0; i < 3; i++) {
            int idx = tid + i * 128;
            if (idx < NR_ * 8) {
                int r = idx >> 3, kq = idx & 7;
                cp_async16(smem_u32(&Ws[0][r][kq]), &W4[((size_t)k * NR_ + r) * 96 + kq]);
            }
        }
        cp_commit();
    }
    int buf = 0;
    for (int it = 0; it < 12; it++) {
        if (it + 1 < 12) {
            int k0n = (it + 1) * 8;
            #pragma unroll
            for (int i = 0; i < 8; i++) {
                int idx = tid + i * 128;
                int r = idx >> 3, kq = idx & 7;
                cp_async16(smem_u32(&Us[buf ^ 1][r][kq]),
                           &U4[((size_t)z * L_ + p0 + r) * 96 + k0n + kq]);
            }
            #pragma unroll
            for (int i = 0; i < 3; i++) {
                int idx = tid + i * 128;
                if (idx < NR_ * 8) {
                    int r = idx >> 3, kq = idx & 7;
                    cp_async16(smem_u32(&Ws[buf ^ 1][r][kq]),
                               &W4[((size_t)k * NR_ + r) * 96 + k0n + kq]);
                }
            }
            cp_commit();
            cp_wait<1>();
        } else {
            cp_wait<0>();
        }
        __syncthreads();
        #pragma unroll
        for (int kq = 0; kq < 8; kq++) {
            float4 u4[4], w4[11];
            #pragma unroll
            for (int i = 0; i < 4; i++) u4[i] = Us[buf][pg * 4 + i][kq];
            #pragma unroll
            for (int j = 0; j < 11; j++) w4[j] = Ws[buf][rq + 4 * j][kq];
            #pragma unroll
            for (int i = 0; i < 4; i++)
                #pragma unroll
                for (int j = 0; j < 11; j++)
                    acc[i][j] += u4[i].x * w4[j].x + u4[i].y * w4[j].y +
                                 u4[i].z * w4[j].z + u4[i].w * w4[j].w;
        }
        __syncthreads();
        buf ^= 1;
    }
    #pragma unroll
    for (int i = 0; i < 4; i++) {
        int p = p0 + pg * 4 + i;
        if (p < L_) {
            float* ob = g_xdbl + ((size_t)z * L_ + p) * NR_;
            #pragma unroll
            for (int j = 0; j < 11; j++) ob[rq + 4 * j] = acc[i][j];
        }
    }
}

// ---------------- scan pass 1: local scan, x_dbl slab in smem, u prefetched ----------------
__global__ __launch_bounds__(128) void k_scan1(const float* __restrict__ A_log,
                                               const float* __restrict__ DTW,
                                               const float* __restrict__ DTB) {
    int z = blockIdx.z;
    int k = z >> 2;
    int tid = threadIdx.x;
    int d = blockIdx.y * 128 + tid;
    int c = blockIdx.x;
    __shared__ float4 sx[LCH_ * 11];
    {
        const float4* src = (const float4*)(g_xdbl + ((size_t)z * L_ + c * LCH_) * NR_);
        #pragma unroll
        for (int i = 0; i < 6; i++) {
            int idx = tid + i * 128;
            if (idx < LCH_ * 11) sx[idx] = src[idx];
        }
    }
    u64 wp[6];
    {
        const float* w = DTW + ((size_t)k * DIN_ + d) * 12;
        #pragma unroll
        for (int i = 0; i < 6; i++) wp[i] = pack2(w[2 * i], w[2 * i + 1]);
    }
    float bias = DTB[k * DIN_ + d];
    bool pok = true;
    #pragma unroll
    for (int n = 0; n < NS_; n++) {
        float an = -__expf(A_log[d * NS_ + n]);
        if (fabsf(an + (float)(n + 1)) > 1e-4f * (float)(n + 1)) pok = false;
    }
    const float* ul = g_u + ((size_t)z * L_ + c * LCH_) * DIN_ + d;
    u64 h2[8];
    #pragma unroll
    for (int i = 0; i < 8; i++) h2[i] = pack2(0.f, 0.f);
    float rprod = 1.f, sdel = 0.f;
    __syncthreads();
    float uu_c = ul[0];
    #pragma unroll 2
    for (int s = 0; s < LCH_; s++) {
        float uu_n = (s + 1 < LCH_) ? ul[(size_t)(s + 1) * DIN_] : 0.f;
        const ulonglong2* rp = (const ulonglong2*)&sx[s * 11];
        ulonglong2 X0 = rp[0], X1 = rp[1], X2 = rp[2];
        u64 s2 = mul2(X0.x, wp[0]);
        s2 = fma2(X0.y, wp[1], s2);
        s2 = fma2(X1.x, wp[2], s2);
        s2 = fma2(X1.y, wp[3], s2);
        s2 = fma2(X2.x, wp[4], s2);
        s2 = fma2(X2.y, wp[5], s2);
        float lo, hi; unpack2(s2, lo, hi);
        float sv = lo + hi + bias;
        float t = __expf(sv);
        float w1t = 1.f + t;
        float de = (sv > 20.f) ? sv : __logf(w1t);
        float du = de * uu_c;
        u64 du2 = pack2(du, du);
        u64 e2[8];
        if (pok) {
            float r = rcp_approx(w1t);      // exp(-softplus(sv))
            decay_from_r(r, e2);
            rprod *= r;
        } else {
            float ee[16];
            exp_general(de, A_log, d, ee);
            #pragma unroll
            for (int i = 0; i < 8; i++) e2[i] = pack2(ee[2 * i], ee[2 * i + 1]);
            sdel += de;
        }
        ulonglong2 B0 = rp[3], B1 = rp[4], B2 = rp[5], B3 = rp[6];
        h2[0] = fma2(e2[0], h2[0], mul2(du2, B0.x));
        h2[1] = fma2(e2[1], h2[1], mul2(du2, B0.y));
        h2[2] = fma2(e2[2], h2[2], mul2(du2, B1.x));
        h2[3] = fma2(e2[3], h2[3], mul2(du2, B1.y));
        h2[4] = fma2(e2[4], h2[4], mul2(du2, B2.x));
        h2[5] = fma2(e2[5], h2[5], mul2(du2, B2.y));
        h2[6] = fma2(e2[6], h2[6], mul2(du2, B3.x));
        h2[7] = fma2(e2[7], h2[7], mul2(du2, B3.y));
        uu_c = uu_n;
    }
    u64* q = g_Q + ((size_t)z * NCH_ + c) * 8 * DIN_ + d;
    #pragma unroll
    for (int i = 0; i < 8; i++) q[(size_t)i * DIN_] = h2[i];
    g_S[((size_t)z * NCH_ + c) * DIN_ + d] = pok ? rprod : sdel;
}

// ---------------- scan fix: prefix over chunks (parallel over z x dgroup, prefetched) ----------------
__global__ __launch_bounds__(128) void k_fix(const float* __restrict__ A_log) {
    int z = blockIdx.x;
    int dg = blockIdx.y;
    int d = dg * 128 + threadIdx.x;
    bool pok = true;
    float a2[NS_];
    #pragma unroll
    for (int n = 0; n < NS_; n++) {
        float an = -__expf(A_log[d * NS_ + n]);
        a2[n] = an * LOG2E;
        if (fabsf(an + (float)(n + 1)) > 1e-4f * (float)(n + 1)) pok = false;
    }
    const u64* Q = g_Q + (size_t)z * NCH_ * 8 * DIN_ + d;
    u64* H = g_Hs + (size_t)z * NCH_ * 8 * DIN_ + d;
    const float* S = g_S + (size_t)z * NCH_ * DIN_ + d;
    u64 hs2[8];
    #pragma unroll
    for (int i = 0; i < 8; i++) hs2[i] = pack2(0.f, 0.f);
    u64 qc[8]; float Sc;
    #pragma unroll
    for (int i = 0; i < 8; i++) qc[i] = Q[(size_t)i * DIN_];
    Sc = S[0];
    for (int c = 0; c < NCH_; c++) {
        u64 qn[8]; float Sn = 0.f;
        if (c + 1 < NCH_) {
            const u64* Qn = Q + (size_t)(c + 1) * 8 * DIN_;
            #pragma unroll
            for (int i = 0; i < 8; i++) qn[i] = Qn[(size_t)i * DIN_];
            Sn = S[(size_t)(c + 1) * DIN_];
        }
        u64* Hc = H + (size_t)c * 8 * DIN_;
        #pragma unroll
        for (int i = 0; i < 8; i++) Hc[(size_t)i * DIN_] = hs2[i];
        u64 e2[8];
        if (pok) {
            decay_from_r(Sc, e2);        // Sc = prod of r over chunk
        } else {
            float ee[16];
            #pragma unroll
            for (int n = 0; n < NS_; n++) ee[n] = exp2f(a2[n] * Sc);
            #pragma unroll
            for (int i = 0; i < 8; i++) e2[i] = pack2(ee[2 * i], ee[2 * i + 1]);
        }
        #pragma unroll
        for (int i = 0; i < 8; i++) hs2[i] = fma2(e2[i], hs2[i], qc[i]);
        #pragma unroll
        for (int i = 0; i < 8; i++) qc[i] = qn[i];
        Sc = Sn;
    }
}

// ---------------- scan pass 2: replay with h_start, smem slab, u/z prefetched ----------------
__global__ __launch_bounds__(128) void k_scan2(const float* __restrict__ A_log,
                                               const float* __restrict__ DTW,
                                               const float* __restrict__ DTB,
                                               const float* __restrict__ Dsk) {
    int z = blockIdx.z;
    int k = z >> 2, b = z & 3;
    int tid = threadIdx.x;
    int d = blockIdx.y * 128 + tid;
    int c = blockIdx.x;
    __shared__ float4 sx[LCH_ * 11];
    __shared__ int ls[LCH_];
    {
        const float4* src = (const float4*)(g_xdbl + ((size_t)z * L_ + c * LCH_) * NR_);
        #pragma unroll
        for (int i = 0; i < 6; i++) {
            int idx = tid + i * 128;
            if (idx < LCH_ * 11) sx[idx] = src[idx];
        }
    }
    if (tid < LCH_) ls[tid] = perm_idx(k, c * LCH_ + tid);
    u64 wp[6];
    {
        const float* w = DTW + ((size_t)k * DIN_ + d) * 12;
        #pragma unroll
        for (int i = 0; i < 6; i++) wp[i] = pack2(w[2 * i], w[2 * i + 1]);
    }
    float bias = DTB[k * DIN_ + d];
    bool pok = true;
    #pragma unroll
    for (int n = 0; n < NS_; n++) {
        float an = -__expf(A_log[d * NS_ + n]);
        if (fabsf(an + (float)(n + 1)) > 1e-4f * (float)(n + 1)) pok = false;
    }
    const float* ul = g_u + ((size_t)z * L_ + c * LCH_) * DIN_ + d;
    const u64* H = g_Hs + ((size_t)z * NCH_ + c) * 8 * DIN_ + d;
    u64 h2[8];
    #pragma unroll
    for (int i = 0; i < 8; i++) h2[i] = H[(size_t)i * DIN_];
    float dsk = Dsk[d];
    size_t bL = (size_t)b * L_;
    __syncthreads();
    float uu_c = ul[0];
    int l_c = ls[0];
    float zv_c = g_xz[(bL + l_c) * (2 * DIN_) + DIN_ + d];
    #pragma unroll 2
    for (int s = 0; s < LCH_; s++) {
        float uu_n = 0.f, zv_n = 0.f; int l_n = 0;
        if (s + 1 < LCH_) {
            uu_n = ul[(size_t)(s + 1) * DIN_];
            l_n = ls[s + 1];
            zv_n = g_xz[(bL + l_n) * (2 * DIN_) + DIN_ + d];
        }
        const ulonglong2* rp = (const ulonglong2*)&sx[s * 11];
        ulonglong2 X0 = rp[0], X1 = rp[1], X2 = rp[2];
        u64 s2 = mul2(X0.x, wp[0]);
        s2 = fma2(X0.y, wp[1], s2);
        s2 = fma2(X1.x, wp[2], s2);
        s2 = fma2(X1.y, wp[3], s2);
        s2 = fma2(X2.x, wp[4], s2);
        s2 = fma2(X2.y, wp[5], s2);
        float lo, hi; unpack2(s2, lo, hi);
        float sv = lo + hi + bias;
        float t = __expf(sv);
        float w1t = 1.f + t;
        float de = (sv > 20.f) ? sv : __logf(w1t);
        float du = de * uu_c;
        u64 du2 = pack2(du, du);
        u64 e2[8];
        if (pok) {
            float r = rcp_approx(w1t);
            decay_from_r(r, e2);
        } else {
            float ee[16];
            exp_general(de, A_log, d, ee);
            #pragma unroll
            for (int i = 0; i < 8; i++) e2[i] = pack2(ee[2 * i], ee[2 * i + 1]);
        }
        ulonglong2 B0 = rp[3], B1 = rp[4], B2 = rp[5], B3 = rp[6];
        ulonglong2 C0 = rp[7], C1 = rp[8], C2 = rp[9], C3 = rp[10];
        h2[0] = fma2(e2[0], h2[0], mul2(du2, B0.x));
        h2[1] = fma2(e2[1], h2[1], mul2(du2, B0.y));
        h2[2] = fma2(e2[2], h2[2], mul2(du2, B1.x));
        h2[3] = fma2(e2[3], h2[3], mul2(du2, B1.y));
        h2[4] = fma2(e2[4], h2[4], mul2(du2, B2.x));
        h2[5] = fma2(e2[5], h2[5], mul2(du2, B2.y));
        h2[6] = fma2(e2[6], h2[6], mul2(du2, B3.x));
        h2[7] = fma2(e2[7], h2[7], mul2(du2, B3.y));
        u64 y2 = mul2(h2[0], C0.x);
        y2 = fma2(h2[1], C0.y, y2);
        y2 = fma2(h2[2], C1.x, y2);
        y2 = fma2(h2[3], C1.y, y2);
        y2 = fma2(h2[4], C2.x, y2);
        y2 = fma2(h2[5], C2.y, y2);
        y2 = fma2(h2[6], C3.x, y2);
        y2 = fma2(h2[7], C3.y, y2);
        float ylo, yhi; unpack2(y2, ylo, yhi);
        float y = ylo + yhi + dsk * uu_c;
        y *= zv_c / (1.f + __expf(-zv_c));
        g_y[((size_t)z * L_ + l_c) * DIN_ + d] = y;
        uu_c = uu_n; zv_c = zv_n; l_c = l_n;
    }
}

// ---------------- LayerNorm over d, warp-per-row x2 ILP, accumulate per-(z,d) sum of xn ----------------
__global__ __launch_bounds__(384) void k_lnstats(const float* __restrict__ G,
                                                 const float* __restrict__ Bt) {
    int kdir = blockIdx.z, b = blockIdx.y;
    int z = kdir * B_ + b;
    int tid = threadIdx.x;
    int w = tid >> 5, lane = tid & 31;
    int gw = blockIdx.x * 12 + w;
    float gr[12], br[12], acc[12];
    #pragma unroll
    for (int j = 0; j < 12; j++) {
        int d = lane + 32 * j;
        gr[j] = G[d]; br[j] = Bt[d]; acc[j] = 0.f;
    }
    int l = gw;
    for (; l + 192 < L_; l += 384) {
        const float* yr0 = g_y + ((size_t)z * L_ + l) * DIN_;
        const float* yr1 = g_y + ((size_t)z * L_ + l + 192) * DIN_;
        float v0[12], v1[12];
        float sa0 = 0.f, sb0 = 0.f, sa1 = 0.f, sb1 = 0.f;
        #pragma unroll
        for (int j = 0; j < 12; j++) {
            v0[j] = yr0[lane + 32 * j];
            v1[j] = yr1[lane + 32 * j];
        }
        #pragma unroll
        for (int j = 0; j < 12; j++) {
            sa0 += v0[j]; sb0 += v0[j] * v0[j];
            sa1 += v1[j]; sb1 += v1[j] * v1[j];
        }
        #pragma unroll
        for (int o = 16; o; o >>= 1) {
            sa0 += __shfl_xor_sync(0xFFFFFFFFu, sa0, o);
            sb0 += __shfl_xor_sync(0xFFFFFFFFu, sb0, o);
            sa1 += __shfl_xor_sync(0xFFFFFFFFu, sa1, o);
            sb1 += __shfl_xor_sync(0xFFFFFFFFu, sb1, o);
        }
        float mu0 = sa0 * (1.f / DIN_);
        float rstd0 = rsqrtf(sb0 * (1.f / DIN_) - mu0 * mu0 + 1e-5f);
        float mu1 = sa1 * (1.f / DIN_);
        float rstd1 = rsqrtf(sb1 * (1.f / DIN_) - mu1 * mu1 + 1e-5f);
        #pragma unroll
        for (int j = 0; j < 12; j++) {
            acc[j] += (v0[j] - mu0) * rstd0 * gr[j] + br[j];
            acc[j] += (v1[j] - mu1) * rstd1 * gr[j] + br[j];
        }
    }
    for (; l < L_; l += 192) {
        const float* yr = g_y + ((size_t)z * L_ + l) * DIN_;
        float v[12];
        float s1 = 0.f, s2 = 0.f;
        #pragma unroll
        for (int j = 0; j < 12; j++) {
            v[j] = yr[lane + 32 * j];
            s1 += v[j];
            s2 += v[j] * v[j];
        }
        #pragma unroll
        for (int o = 16; o; o >>= 1) {
            s1 += __shfl_xor_sync(0xFFFFFFFFu, s1, o);
            s2 += __shfl_xor_sync(0xFFFFFFFFu, s2, o);
        }
        float mu = s1 * (1.f / DIN_);
        float var = s2 * (1.f / DIN_) - mu * mu;
        float rstd = rsqrtf(var + 1e-5f);
        #pragma unroll
        for (int j = 0; j < 12; j++)
            acc[j] += (v[j] - mu) * rstd * gr[j] + br[j];
    }
    #pragma unroll
    for (int j = 0; j < 12; j++)
        atomicAdd(&g_gsum[z * DIN_ + lane + 32 * j], acc[j]);
}

// ---------------- channel attention ----------------
__global__ void k_attn(const float* __restrict__ RW, const float* __restrict__ RB,
                       const float* __restrict__ SW, const float* __restrict__ SB) {
    int z = blockIdx.x;
    __shared__ float gg[DIN_];
    __shared__ float tt[RED_];
    int d = threadIdx.x;
    int lane = d & 31, wid = d >> 5;
    gg[d] = g_gsum[z * DIN_ + d] * (1.f / (float)L_);
    __syncthreads();
    #pragma unroll
    for (int jj = 0; jj < 4; jj++) {
        int j = wid * 4 + jj;
        float s = 0.f;
        for (int i = lane; i < DIN_; i += 32) s += gg[i] * RW[(size_t)j * DIN_ + i];
        #pragma unroll
        for (int o = 16; o; o >>= 1) s += __shfl_xor_sync(0xFFFFFFFFu, s, o);
        if (lane == 0) {
            float v = s + RB[j];
            tt[j] = 0.5f * v * (1.f + erff(v * 0.70710678118f));
        }
    }
    __syncthreads();
    float s = SB[d];
    #pragma unroll
    for (int j = 0; j < RED_; j++) s += tt[j] * SW[(size_t)d * RED_ + j];
    g_catt[z * DIN_ + d] = 1.f / (1.f + __expf(-s));
}

// ---------------- out = (sum_k y_k * catt_k) @ out_proj.T + bias (FFMA2, y prefetch) ----------------
__global__ __launch_bounds__(128) void k_out(const float* __restrict__ W,
                                             const float* __restrict__ BI,
                                             float* __restrict__ OUT) {
    __shared__ float4 As[16][9];
    __shared__ float4 Ws[192][9];
    int m0 = blockIdx.x * 16;
    int b = m0 / L_;
    int l0 = m0 - b * L_;
    int tid = threadIdx.x;
    int tx = tid & 31, ty = tid >> 5;   // ty 0..3
    int ar = tid >> 3, akq = tid & 7;   // As loader role
    const float4* Y4 = (const float4*)g_y;
    const float4* C4 = (const float4*)g_catt;
    const float4* W4 = (const float4*)W;
    u64 acc2[4][6];
    #pragma unroll
    for (int i = 0; i < 4; i++)
        #pragma unroll
        for (int j = 0; j < 6; j++) acc2[i][j] = pack2(0.f, 0.f);
    // preload y stream for k0 = 0
    float4 ycur[KDIR_];
    #pragma unroll
    for (int dir = 0; dir < KDIR_; dir++)
        ycur[dir] = Y4[((size_t)(dir * B_ + b) * L_ + l0 + ar) * 96 + akq];
    for (int it = 0; it < 12; it++) {
        int k0 = it * 8;
        __syncthreads();
        {
            float4 s = {0.f, 0.f, 0.f, 0.f};
            #pragma unroll
            for (int dir = 0; dir < KDIR_; dir++) {
                float4 c4 = C4[(size_t)(dir * B_ + b) * 96 + k0 + akq];
                s.x += ycur[dir].x * c4.x; s.y += ycur[dir].y * c4.y;
                s.z += ycur[dir].z * c4.z; s.w += ycur[dir].w * c4.w;
            }
            As[ar][akq] = s;
        }
        #pragma unroll
        for (int i = 0; i < 12; i++) {
            int idx = tid + i * 128;
            int r = idx >> 3, kq = idx & 7;
            Ws[r][kq] = W4[(size_t)r * 96 + k0 + kq];
        }
        __syncthreads();
        if (it + 1 < 12) {
            int k0n = k0 + 8;
            #pragma unroll
            for (int dir = 0; dir < KDIR_; dir++)
                ycur[dir] = Y4[((size_t)(dir * B_ + b) * L_ + l0 + ar) * 96 + k0n + akq];
        }
        #pragma unroll
        for (int kq = 0; kq < 8; kq++) {
            ulonglong2 au[4];
            #pragma unroll
            for (int i = 0; i < 4; i++) au[i] = *(const ulonglong2*)&As[ty * 4 + i][kq];
            #pragma unroll
            for (int j = 0; j < 6; j++) {
                ulonglong2 w = *(const ulonglong2*)&Ws[tx + 32 * j][kq];
                #pragma unroll
                for (int i = 0; i < 4; i++) {
                    acc2[i][j] = fma2(au[i].x, w.x, acc2[i][j]);
                    acc2[i][j] = fma2(au[i].y, w.y, acc2[i][j]);
                }
            }
        }
    }
    #pragma unroll
    for (int i = 0; i < 4; i++)
        #pragma unroll
        for (int j = 0; j < 6; j++) {
            float lo, hi; unpack2(acc2[i][j], lo, hi);
            OUT[(size_t)(m0 + ty * 4 + i) * DM_ + tx + 32 * j] = lo + hi + BI[tx + 32 * j];
        }
}

// ---------------- launch ----------------
extern "C" void kernel_launch(void* const* d_in, const int* in_sizes, int n_in,
                              void* d_out, int out_size) {
    const float* x          = (const float*)d_in[0];
    const float* in_proj_w  = (const float*)d_in[1];
    const float* conv_w     = (const float*)d_in[2];
    const float* conv_b     = (const float*)d_in[3];
    const float* x_proj_w   = (const float*)d_in[4];
    const float* dt_w       = (const float*)d_in[5];
    const float* dt_b       = (const float*)d_in[6];
    const float* A_log      = (const float*)d_in[7];
    const float* D_skip     = (const float*)d_in[8];
    const float* out_proj_w = (const float*)d_in[9];
    const float* out_proj_b = (const float*)d_in[10];
    const float* ln_g       = (const float*)d_in[11];
    const float* ln_b       = (const float*)d_in[12];
    const float* red_w      = (const float*)d_in[13];
    const float* red_b      = (const float*)d_in[14];
    const float* sel_w      = (const float*)d_in[15];
    const float* sel_b      = (const float*)d_in[16];
    const float* mask_w     = (const float*)d_in[17];
    const float* mask_b     = (const float*)d_in[18];
    float* out = (float*)d_out;

    k_mask<<<dim3((B_ * L_ + 7) / 8), dim3(32, 8)>>>(x, mask_w, mask_b);
    k_xz<<<dim3(12, 196), 256>>>(x, in_proj_w);
    k_conv<<<dim3(49, 3, KDIR_ * B_), 128>>>(conv_w, conv_b);
    k_xdbl<<<dim3(25, KDIR_ * B_), 128>>>(x_proj_w);
    k_scan1<<<dim3(NCH_, 3, KDIR_ * B_), 128>>>(A_log, dt_w, dt_b);
    k_fix<<<dim3(KDIR_ * B_, 3), 128>>>(A_log);
    k_scan2<<<dim3(NCH_, 3, KDIR_ * B_), 128>>>(A_log, dt_w, dt_b, D_skip);
    k_lnstats<<<dim3(16, B_, KDIR_), 384>>>(ln_g, ln_b);
    k_attn<<<KDIR_ * B_, DIN_>>>(red_w, red_b, sel_w, sel_b);
    k_out<<<dim3(784), 128>>>(out_proj_w, out_proj_b, out);
}